// round 2
// baseline (speedup 1.0000x reference)
#include <cuda_runtime.h>

#define N_NODES   500000
#define E_EDGES   16000000
#define NVEC      (E_EDGES / 4)
#define NBH       4096          // high bins (dst>>7), only 3907 used
#define NBH_USED  3907
#define CHUNK     16384         // edges per partition block
#define NPART     ((E_EDGES + CHUNK - 1) / CHUNK)   // 977
#define NT_GATHER 125000        // threads in gather pass (4 nodes each)

// ---------------------------------------------------------------------------
// Static scratch (allocation-free rule)
// ---------------------------------------------------------------------------
__device__ float         g_outdeg[N_NODES];
__device__ float         g_ds[N_NODES];          // out_deg^-0.5
__device__ float         g_dd[N_NODES];          // in_deg^-0.5
__device__ float         g_xs[N_NODES];          // y * ds (layer-1 message)
__device__ float         g_x2[N_NODES];          // layer-2 message
__device__ unsigned int  g_off[N_NODES + 1];     // CSR offsets (by dst)
__device__ unsigned int  g_hist[NBH];            // high-bin histogram
__device__ unsigned int  g_binOff[NBH + 1];      // high-bin offsets
__device__ unsigned int  g_cursor[NBH];          // allocation cursors
__device__ unsigned int  g_recs[E_EDGES];        // (src<<7)|dstLow, grouped by high bin
__device__ unsigned int  g_srcSorted[E_EDGES];   // src ids, fully sorted by dst

// ---------------------------------------------------------------------------
// 0. zero scratch
// ---------------------------------------------------------------------------
__global__ void zero_kernel() {
    int i = blockIdx.x * blockDim.x + threadIdx.x;
    if (i < N_NODES) g_outdeg[i] = 0.0f;
    if (i < NBH)     g_hist[i] = 0u;
}

// ---------------------------------------------------------------------------
// 1. histogram of dst>>7  +  out-degree (float RED)
// ---------------------------------------------------------------------------
__global__ void hist_kernel(const int4* __restrict__ src4, const int4* __restrict__ dst4) {
    __shared__ unsigned int sh[NBH];
    for (int j = threadIdx.x; j < NBH; j += blockDim.x) sh[j] = 0u;
    __syncthreads();

    int stride = gridDim.x * blockDim.x;
    for (int i = blockIdx.x * blockDim.x + threadIdx.x; i < NVEC; i += stride) {
        int4 s = __ldg(src4 + i);
        int4 d = __ldg(dst4 + i);
        atomicAdd(&g_outdeg[s.x], 1.0f);
        atomicAdd(&g_outdeg[s.y], 1.0f);
        atomicAdd(&g_outdeg[s.z], 1.0f);
        atomicAdd(&g_outdeg[s.w], 1.0f);
        atomicAdd(&sh[d.x >> 7], 1u);
        atomicAdd(&sh[d.y >> 7], 1u);
        atomicAdd(&sh[d.z >> 7], 1u);
        atomicAdd(&sh[d.w >> 7], 1u);
    }
    __syncthreads();
    for (int j = threadIdx.x; j < NBH; j += blockDim.x)
        if (sh[j]) atomicAdd(&g_hist[j], sh[j]);
}

// ---------------------------------------------------------------------------
// 2. exclusive scan of 4096 bins (single block, 1024 threads)
// ---------------------------------------------------------------------------
__global__ void scan_kernel() {
    __shared__ unsigned int bufA[1024], bufB[1024];
    int tid = threadIdx.x;
    unsigned int v[4], s = 0;
#pragma unroll
    for (int j = 0; j < 4; j++) { v[j] = g_hist[tid * 4 + j]; s += v[j]; }
    bufA[tid] = s;
    __syncthreads();
    unsigned int *in = bufA, *out = bufB;
    for (int d = 1; d < 1024; d <<= 1) {
        unsigned int x = in[tid];
        if (tid >= d) x += in[tid - d];
        out[tid] = x;
        __syncthreads();
        unsigned int* t = in; in = out; out = t;
    }
    unsigned int incl = in[tid];
    unsigned int run = incl - s;   // exclusive base
#pragma unroll
    for (int j = 0; j < 4; j++) {
        g_binOff[tid * 4 + j] = run;
        g_cursor[tid * 4 + j] = run;
        run += v[j];
    }
    if (tid == 1023) g_binOff[NBH] = E_EDGES;
    if (tid == 0)    g_off[N_NODES] = E_EDGES;
}

// ---------------------------------------------------------------------------
// 3. partition edges by high bin (dst>>7); record = (src<<7)|(dst&127)
// ---------------------------------------------------------------------------
__global__ __launch_bounds__(256) void part_kernel(const int* __restrict__ src,
                                                   const int* __restrict__ dst) {
    __shared__ unsigned int sh_cnt[NBH];
    __shared__ unsigned int sh_base[NBH];
    int tid = threadIdx.x;
    int lo = blockIdx.x * CHUNK;
    int hi = lo + CHUNK; if (hi > E_EDGES) hi = E_EDGES;

    for (int j = tid; j < NBH; j += 256) sh_cnt[j] = 0u;
    __syncthreads();
    for (int i = lo + tid; i < hi; i += 256) {
        int d = __ldg(dst + i);
        atomicAdd(&sh_cnt[d >> 7], 1u);
    }
    __syncthreads();
    for (int j = tid; j < NBH; j += 256) {
        unsigned int c = sh_cnt[j];
        sh_base[j] = c ? atomicAdd(&g_cursor[j], c) : 0u;
        sh_cnt[j] = 0u;
    }
    __syncthreads();
    for (int i = lo + tid; i < hi; i += 256) {
        int s = __ldg(src + i);
        int d = __ldg(dst + i);
        int key = d >> 7;
        unsigned int r = atomicAdd(&sh_cnt[key], 1u);
        g_recs[sh_base[key] + r] = ((unsigned int)s << 7) | (unsigned int)(d & 127);
    }
}

// ---------------------------------------------------------------------------
// 4. per-high-bin sort by low 7 bits; one warp per bin, thread-private
//    smem counters (NO atomics). Emits g_srcSorted + CSR offsets g_off.
// ---------------------------------------------------------------------------
__global__ __launch_bounds__(128) void sort2_kernel() {
    __shared__ unsigned short priv[4][128 * 32];
    int warpInBlk = threadIdx.x >> 5;
    int lane = threadIdx.x & 31;
    int wb = blockIdx.x * 4 + warpInBlk;       // high bin id
    if (wb >= NBH_USED) return;
    unsigned short* my = priv[warpInBlk];

    unsigned int lo = g_binOff[wb];
    unsigned int hi = g_binOff[wb + 1];

#pragma unroll 8
    for (int low = 0; low < 128; low++) my[low * 32 + lane] = 0;
    __syncwarp();

    // phase 1: private counts
    for (unsigned int i = lo + lane; i < hi; i += 32) {
        unsigned int rec = __ldg(g_recs + i);
        int low = rec & 127;
        my[low * 32 + lane]++;
    }
    __syncwarp();

    // phase 2: exclusive prefix in (low-major, lane) order; emit offsets
    unsigned int running = 0;
    for (int low = 0; low < 128; low++) {
        unsigned int v = my[low * 32 + lane];
        unsigned int x = v;
#pragma unroll
        for (int o = 1; o < 32; o <<= 1) {
            unsigned int y = __shfl_up_sync(0xffffffffu, x, o);
            if (lane >= o) x += y;
        }
        unsigned int excl = x - v;
        unsigned int tot  = __shfl_sync(0xffffffffu, x, 31);
        my[low * 32 + lane] = (unsigned short)(running + excl);
        if (lane == 0) {
            int node = wb * 128 + low;
            if (node < N_NODES) g_off[node] = lo + running;
        }
        running += tot;
    }
    __syncwarp();

    // phase 3: place src ids
    for (unsigned int i = lo + lane; i < hi; i += 32) {
        unsigned int rec = __ldg(g_recs + i);
        int low = rec & 127;
        unsigned int p = my[low * 32 + lane];
        my[low * 32 + lane] = (unsigned short)(p + 1);
        g_srcSorted[lo + p] = rec >> 7;
    }
}

// ---------------------------------------------------------------------------
// 5. init: degree norms, sign fix, first message
// ---------------------------------------------------------------------------
__global__ void init_kernel(const float* __restrict__ y_in, float* __restrict__ y) {
    int i = blockIdx.x * blockDim.x + threadIdx.x;
    if (i >= N_NODES) return;
    float ds = rsqrtf(fmaxf(g_outdeg[i], 1.0f));
    float indeg = (float)(g_off[i + 1] - g_off[i]);
    float dd = rsqrtf(fmaxf(indeg, 1.0f));
    g_ds[i] = ds;
    g_dd[i] = dd;
    float yv = y_in[i];
    yv = (yv == 0.0f) ? -1.0f : yv;
    y[i]    = yv;
    g_xs[i] = yv * ds;
}

// ---------------------------------------------------------------------------
// gather helper: sum vals[srcSorted[lo..hi)] with 4-way MLP
// ---------------------------------------------------------------------------
__device__ __forceinline__ float seg_gather(const float* __restrict__ vals,
                                            unsigned int lo, unsigned int hi) {
    float a0 = 0.f, a1 = 0.f, a2 = 0.f, a3 = 0.f;
    unsigned int i = lo;
    for (; i + 4 <= hi; i += 4) {
        unsigned int s0 = __ldg(g_srcSorted + i);
        unsigned int s1 = __ldg(g_srcSorted + i + 1);
        unsigned int s2 = __ldg(g_srcSorted + i + 2);
        unsigned int s3 = __ldg(g_srcSorted + i + 3);
        a0 += __ldg(vals + s0);
        a1 += __ldg(vals + s1);
        a2 += __ldg(vals + s2);
        a3 += __ldg(vals + s3);
    }
    for (; i < hi; i++) a0 += __ldg(vals + __ldg(g_srcSorted + i));
    return (a0 + a1) + (a2 + a3);
}

// ---------------------------------------------------------------------------
// 6a. fused pass A: agg = A·xs ; full layer-1 (fc+resid+LN+PReLU) + layer-2 fc
//     -> g_x2  (no atomics, register accumulation, 4 nodes/thread)
// ---------------------------------------------------------------------------
__global__ __launch_bounds__(256) void passA_kernel(const float* __restrict__ y,
        const float* __restrict__ W1,  const float* __restrict__ b1,
        const float* __restrict__ Wres,
        const float* __restrict__ lng, const float* __restrict__ lnb,
        const float* __restrict__ pa,
        const float* __restrict__ W2,  const float* __restrict__ b2) {
    int t = blockIdx.x * blockDim.x + threadIdx.x;
    if (t >= NT_GATHER) return;
    int n0 = t * 4;
    unsigned int lo = g_off[n0];
    float alpha = __ldg(pa);
    float bias2 = __ldg(b2);
#pragma unroll
    for (int k = 0; k < 4; k++) {
        int n = n0 + k;
        unsigned int hi = g_off[n + 1];
        float a = seg_gather(g_xs, lo, hi);
        lo = hi;

        float yv = y[n];
        float ds = g_ds[n];
        float dd = g_dd[n];

        float r[8]; float mu = 0.f;
#pragma unroll
        for (int j = 0; j < 8; j++) {
            r[j] = (a * __ldg(W1 + j) + __ldg(b1 + j)) * dd + yv * __ldg(Wres + j);
            mu += r[j];
        }
        mu *= 0.125f;
        float var = 0.f;
#pragma unroll
        for (int j = 0; j < 8; j++) { float u = r[j] - mu; var += u * u; }
        var *= 0.125f;
        float inv = rsqrtf(var + 1e-5f);
        float dot = 0.f;
#pragma unroll
        for (int j = 0; j < 8; j++) {
            float u = (r[j] - mu) * inv * __ldg(lng + j) + __ldg(lnb + j);
            u = (u >= 0.f) ? u : alpha * u;
            dot += u * __ldg(W2 + j);
        }
        g_x2[n] = ds * dot + bias2;
    }
}

// ---------------------------------------------------------------------------
// 6b. fused pass B: agg2 = A·x2 ; y += dd*agg2 ; xs = y*ds
// ---------------------------------------------------------------------------
__global__ __launch_bounds__(256) void passB_kernel(float* __restrict__ y) {
    int t = blockIdx.x * blockDim.x + threadIdx.x;
    if (t >= NT_GATHER) return;
    int n0 = t * 4;
    unsigned int lo = g_off[n0];
#pragma unroll
    for (int k = 0; k < 4; k++) {
        int n = n0 + k;
        unsigned int hi = g_off[n + 1];
        float a = seg_gather(g_x2, lo, hi);
        lo = hi;
        float yv = y[n] + a * g_dd[n];
        y[n]    = yv;
        g_xs[n] = yv * g_ds[n];
    }
}

// ---------------------------------------------------------------------------
// launch
// ---------------------------------------------------------------------------
extern "C" void kernel_launch(void* const* d_in, const int* in_sizes, int n_in,
                              void* d_out, int out_size) {
    const float* y_in = (const float*)d_in[0];
    const int*   src  = (const int*)d_in[1];
    const int*   dst  = (const int*)d_in[2];
    const float* W1   = (const float*)d_in[3];
    const float* b1   = (const float*)d_in[4];
    const float* Wres = (const float*)d_in[5];
    const float* lng  = (const float*)d_in[6];
    const float* lnb  = (const float*)d_in[7];
    const float* pa   = (const float*)d_in[8];
    const float* W2   = (const float*)d_in[9];
    const float* b2   = (const float*)d_in[10];
    float* y = (float*)d_out;

    const int TB = 256;
    int nb_n = (N_NODES + TB - 1) / TB;
    int nb_g = (NT_GATHER + TB - 1) / TB;

    zero_kernel<<<nb_n, TB>>>();
    hist_kernel<<<592, TB>>>((const int4*)src, (const int4*)dst);
    scan_kernel<<<1, 1024>>>();
    part_kernel<<<NPART, 256>>>(src, dst);
    sort2_kernel<<<(NBH_USED + 3) / 4, 128>>>();
    init_kernel<<<nb_n, TB>>>(y_in, y);

    for (int l = 0; l < 4; l++) {
        passA_kernel<<<nb_g, TB>>>(y, W1, b1, Wres, lng, lnb, pa, W2, b2);
        passB_kernel<<<nb_g, TB>>>(y);
    }
}

// round 3
// speedup vs baseline: 1.1054x; 1.1054x over previous
#include <cuda_runtime.h>

#define N_NODES   500000
#define E_EDGES   16000000
#define NVEC      (E_EDGES / 4)
#define NT_GATHER 125000                 // gather threads (4 nodes each)
#define SCAN_TILE 1024                   // elems per scan block
#define NB_SCAN   ((N_NODES + SCAN_TILE - 1) / SCAN_TILE)   // 489

// ---------------------------------------------------------------------------
// Static scratch (allocation-free rule)
// ---------------------------------------------------------------------------
__device__ unsigned int  g_incnt[N_NODES];       // in-degree counts
__device__ unsigned int  g_outcnt[N_NODES];      // out-degree counts
__device__ float         g_ds[N_NODES];          // out_deg^-0.5
__device__ float         g_dd[N_NODES];          // in_deg^-0.5
__device__ float         g_xs[N_NODES];          // y * ds (layer-1 message)
__device__ float         g_x2[N_NODES];          // layer-2 message
__device__ unsigned int  g_off[N_NODES + 1];     // CSR offsets (by dst)
__device__ unsigned int  g_cursor[N_NODES];      // scatter cursors
__device__ unsigned int  g_blk[NB_SCAN];         // per-block sums for scan
__device__ unsigned int  g_srcSorted[E_EDGES];   // src ids grouped by dst

// ---------------------------------------------------------------------------
// 0. zero counters
// ---------------------------------------------------------------------------
__global__ void zero_kernel() {
    int i = blockIdx.x * blockDim.x + threadIdx.x;
    if (i < N_NODES) { g_incnt[i] = 0u; g_outcnt[i] = 0u; }
}

// ---------------------------------------------------------------------------
// 1. one edge pass: in-degree + out-degree (uint REDs)
// ---------------------------------------------------------------------------
__global__ void count_kernel(const int4* __restrict__ src4, const int4* __restrict__ dst4) {
    int i = blockIdx.x * blockDim.x + threadIdx.x;
    if (i >= NVEC) return;
    int4 s = __ldg(src4 + i);
    int4 d = __ldg(dst4 + i);
    atomicAdd(&g_outcnt[s.x], 1u);
    atomicAdd(&g_outcnt[s.y], 1u);
    atomicAdd(&g_outcnt[s.z], 1u);
    atomicAdd(&g_outcnt[s.w], 1u);
    atomicAdd(&g_incnt[d.x], 1u);
    atomicAdd(&g_incnt[d.y], 1u);
    atomicAdd(&g_incnt[d.z], 1u);
    atomicAdd(&g_incnt[d.w], 1u);
}

// ---------------------------------------------------------------------------
// 2a. scan stage 1: per-block local exclusive scan of in-degrees
// ---------------------------------------------------------------------------
__global__ __launch_bounds__(256) void scan1_kernel() {
    __shared__ unsigned int sh[256];
    int tid  = threadIdx.x;
    int base = blockIdx.x * SCAN_TILE + tid * 4;
    unsigned int v[4], s = 0;
#pragma unroll
    for (int j = 0; j < 4; j++) {
        int idx = base + j;
        v[j] = (idx < N_NODES) ? g_incnt[idx] : 0u;
        s += v[j];
    }
    // block inclusive scan of thread sums
    unsigned int x = s;
    int lane = tid & 31, warp = tid >> 5;
#pragma unroll
    for (int o = 1; o < 32; o <<= 1) {
        unsigned int y = __shfl_up_sync(0xffffffffu, x, o);
        if (lane >= o) x += y;
    }
    __shared__ unsigned int wsum[8];
    if (lane == 31) wsum[warp] = x;
    __syncthreads();
    if (warp == 0) {
        unsigned int w = (lane < 8) ? wsum[lane] : 0u;
#pragma unroll
        for (int o = 1; o < 8; o <<= 1) {
            unsigned int y = __shfl_up_sync(0xffffffffu, w, o);
            if (lane >= o) w += y;
        }
        if (lane < 8) wsum[lane] = w;
    }
    __syncthreads();
    unsigned int excl = x - s + (warp ? wsum[warp - 1] : 0u);
#pragma unroll
    for (int j = 0; j < 4; j++) {
        int idx = base + j;
        if (idx < N_NODES) g_off[idx] = excl;   // local exclusive, fixed in stage 3
        excl += v[j];
    }
    if (tid == 255) g_blk[blockIdx.x] = excl;   // block total
    (void)sh;
}

// ---------------------------------------------------------------------------
// 2b. scan stage 2: exclusive scan of block sums (single block)
// ---------------------------------------------------------------------------
__global__ __launch_bounds__(512) void scan2_kernel() {
    __shared__ unsigned int bufA[512], bufB[512];
    int tid = threadIdx.x;
    unsigned int v = (tid < NB_SCAN) ? g_blk[tid] : 0u;
    bufA[tid] = v;
    __syncthreads();
    unsigned int *in = bufA, *out = bufB;
    for (int d = 1; d < 512; d <<= 1) {
        unsigned int x = in[tid];
        if (tid >= d) x += in[tid - d];
        out[tid] = x;
        __syncthreads();
        unsigned int* t = in; in = out; out = t;
    }
    if (tid < NB_SCAN) g_blk[tid] = in[tid] - v;   // exclusive
}

// ---------------------------------------------------------------------------
// 2c. scan stage 3 + full node init: finalize offsets, cursors, degree norms,
//     y sign fix, first message
// ---------------------------------------------------------------------------
__global__ __launch_bounds__(256) void scan3_init_kernel(const float* __restrict__ y_in,
                                                         float* __restrict__ y) {
    int tid  = threadIdx.x;
    unsigned int add = g_blk[blockIdx.x];
    int base = blockIdx.x * SCAN_TILE + tid * 4;
#pragma unroll
    for (int j = 0; j < 4; j++) {
        int i = base + j;
        if (i >= N_NODES) break;
        unsigned int off = g_off[i] + add;
        g_off[i]    = off;
        g_cursor[i] = off;
        float ds = rsqrtf(fmaxf((float)g_outcnt[i], 1.0f));
        float dd = rsqrtf(fmaxf((float)g_incnt[i], 1.0f));
        g_ds[i] = ds;
        g_dd[i] = dd;
        float yv = y_in[i];
        yv = (yv == 0.0f) ? -1.0f : yv;
        y[i]    = yv;
        g_xs[i] = yv * ds;
    }
    if (blockIdx.x == 0 && tid == 0) g_off[N_NODES] = E_EDGES;
}

// ---------------------------------------------------------------------------
// 3. direct counting-sort scatter: srcSorted grouped by dst
// ---------------------------------------------------------------------------
__global__ void scatter_kernel(const int4* __restrict__ src4, const int4* __restrict__ dst4) {
    int i = blockIdx.x * blockDim.x + threadIdx.x;
    if (i >= NVEC) return;
    int4 s = __ldg(src4 + i);
    int4 d = __ldg(dst4 + i);
    unsigned int p0 = atomicAdd(&g_cursor[d.x], 1u);
    unsigned int p1 = atomicAdd(&g_cursor[d.y], 1u);
    unsigned int p2 = atomicAdd(&g_cursor[d.z], 1u);
    unsigned int p3 = atomicAdd(&g_cursor[d.w], 1u);
    g_srcSorted[p0] = (unsigned int)s.x;
    g_srcSorted[p1] = (unsigned int)s.y;
    g_srcSorted[p2] = (unsigned int)s.z;
    g_srcSorted[p3] = (unsigned int)s.w;
}

// ---------------------------------------------------------------------------
// gather helper: sum vals[srcSorted[lo..hi)] with 4-way MLP
// ---------------------------------------------------------------------------
__device__ __forceinline__ float seg_gather(const float* __restrict__ vals,
                                            unsigned int lo, unsigned int hi) {
    float a0 = 0.f, a1 = 0.f, a2 = 0.f, a3 = 0.f;
    unsigned int i = lo;
    for (; i + 4 <= hi; i += 4) {
        unsigned int s0 = __ldg(g_srcSorted + i);
        unsigned int s1 = __ldg(g_srcSorted + i + 1);
        unsigned int s2 = __ldg(g_srcSorted + i + 2);
        unsigned int s3 = __ldg(g_srcSorted + i + 3);
        a0 += __ldg(vals + s0);
        a1 += __ldg(vals + s1);
        a2 += __ldg(vals + s2);
        a3 += __ldg(vals + s3);
    }
    for (; i < hi; i++) a0 += __ldg(vals + __ldg(g_srcSorted + i));
    return (a0 + a1) + (a2 + a3);
}

// ---------------------------------------------------------------------------
// 4a. fused pass A: agg = A·xs ; fc+resid+LN+PReLU + layer-2 fc -> g_x2
// ---------------------------------------------------------------------------
__global__ __launch_bounds__(256) void passA_kernel(const float* __restrict__ y,
        const float* __restrict__ W1,  const float* __restrict__ b1,
        const float* __restrict__ Wres,
        const float* __restrict__ lng, const float* __restrict__ lnb,
        const float* __restrict__ pa,
        const float* __restrict__ W2,  const float* __restrict__ b2) {
    int t = blockIdx.x * blockDim.x + threadIdx.x;
    if (t >= NT_GATHER) return;
    int n0 = t * 4;
    unsigned int lo = g_off[n0];
    float alpha = __ldg(pa);
    float bias2 = __ldg(b2);
#pragma unroll
    for (int k = 0; k < 4; k++) {
        int n = n0 + k;
        unsigned int hi = g_off[n + 1];
        float a = seg_gather(g_xs, lo, hi);
        lo = hi;

        float yv = y[n];
        float ds = g_ds[n];
        float dd = g_dd[n];

        float r[8]; float mu = 0.f;
#pragma unroll
        for (int j = 0; j < 8; j++) {
            r[j] = (a * __ldg(W1 + j) + __ldg(b1 + j)) * dd + yv * __ldg(Wres + j);
            mu += r[j];
        }
        mu *= 0.125f;
        float var = 0.f;
#pragma unroll
        for (int j = 0; j < 8; j++) { float u = r[j] - mu; var += u * u; }
        var *= 0.125f;
        float inv = rsqrtf(var + 1e-5f);
        float dot = 0.f;
#pragma unroll
        for (int j = 0; j < 8; j++) {
            float u = (r[j] - mu) * inv * __ldg(lng + j) + __ldg(lnb + j);
            u = (u >= 0.f) ? u : alpha * u;
            dot += u * __ldg(W2 + j);
        }
        g_x2[n] = ds * dot + bias2;
    }
}

// ---------------------------------------------------------------------------
// 4b. fused pass B: agg2 = A·x2 ; y += dd*agg2 ; xs = y*ds
// ---------------------------------------------------------------------------
__global__ __launch_bounds__(256) void passB_kernel(float* __restrict__ y) {
    int t = blockIdx.x * blockDim.x + threadIdx.x;
    if (t >= NT_GATHER) return;
    int n0 = t * 4;
    unsigned int lo = g_off[n0];
#pragma unroll
    for (int k = 0; k < 4; k++) {
        int n = n0 + k;
        unsigned int hi = g_off[n + 1];
        float a = seg_gather(g_x2, lo, hi);
        lo = hi;
        float yv = y[n] + a * g_dd[n];
        y[n]    = yv;
        g_xs[n] = yv * g_ds[n];
    }
}

// ---------------------------------------------------------------------------
// launch
// ---------------------------------------------------------------------------
extern "C" void kernel_launch(void* const* d_in, const int* in_sizes, int n_in,
                              void* d_out, int out_size) {
    const float* y_in = (const float*)d_in[0];
    const int*   src  = (const int*)d_in[1];
    const int*   dst  = (const int*)d_in[2];
    const float* W1   = (const float*)d_in[3];
    const float* b1   = (const float*)d_in[4];
    const float* Wres = (const float*)d_in[5];
    const float* lng  = (const float*)d_in[6];
    const float* lnb  = (const float*)d_in[7];
    const float* pa   = (const float*)d_in[8];
    const float* W2   = (const float*)d_in[9];
    const float* b2   = (const float*)d_in[10];
    float* y = (float*)d_out;

    const int TB = 256;
    int nb_n = (N_NODES + TB - 1) / TB;
    int nb_e = (NVEC + TB - 1) / TB;
    int nb_g = (NT_GATHER + TB - 1) / TB;

    zero_kernel<<<nb_n, TB>>>();
    count_kernel<<<nb_e, TB>>>((const int4*)src, (const int4*)dst);
    scan1_kernel<<<NB_SCAN, 256>>>();
    scan2_kernel<<<1, 512>>>();
    scan3_init_kernel<<<NB_SCAN, 256>>>(y_in, y);
    scatter_kernel<<<nb_e, TB>>>((const int4*)src, (const int4*)dst);

    for (int l = 0; l < 4; l++) {
        passA_kernel<<<nb_g, TB>>>(y, W1, b1, Wres, lng, lnb, pa, W2, b2);
        passB_kernel<<<nb_g, TB>>>(y);
    }
}

// round 4
// speedup vs baseline: 1.2304x; 1.1131x over previous
#include <cuda_runtime.h>

#define N_NODES   500000
#define E_EDGES   16000000
#define NVEC      (E_EDGES / 4)
#define NWARPS    (N_NODES / 32)         // 15625 warps, 32 nodes each
#define SCAN_TILE 1024
#define NB_SCAN   ((N_NODES + SCAN_TILE - 1) / SCAN_TILE)   // 489

// ---------------------------------------------------------------------------
// Static scratch (allocation-free rule)
// ---------------------------------------------------------------------------
__device__ unsigned int  g_incnt[N_NODES];
__device__ unsigned int  g_outcnt[N_NODES];
__device__ float         g_ds[N_NODES];          // out_deg^-0.5
__device__ float         g_dd[N_NODES];          // in_deg^-0.5
__device__ float         g_xs[N_NODES];          // y * ds
__device__ float         g_x2[N_NODES];          // layer-2 message
__device__ unsigned int  g_off[N_NODES + 1];     // CSR offsets (by dst)
__device__ unsigned int  g_cursor[N_NODES];
__device__ unsigned int  g_blk[NB_SCAN];
__device__ unsigned int  g_srcSorted[E_EDGES];   // src ids grouped by dst

// ---------------------------------------------------------------------------
// 0. zero counters
// ---------------------------------------------------------------------------
__global__ void zero_kernel() {
    int i = blockIdx.x * blockDim.x + threadIdx.x;
    if (i < N_NODES) { g_incnt[i] = 0u; g_outcnt[i] = 0u; }
}

// ---------------------------------------------------------------------------
// 1. one edge pass: in-degree + out-degree (uint REDs)
// ---------------------------------------------------------------------------
__global__ void count_kernel(const int4* __restrict__ src4, const int4* __restrict__ dst4) {
    int i = blockIdx.x * blockDim.x + threadIdx.x;
    if (i >= NVEC) return;
    int4 s = __ldg(src4 + i);
    int4 d = __ldg(dst4 + i);
    atomicAdd(&g_outcnt[s.x], 1u);
    atomicAdd(&g_outcnt[s.y], 1u);
    atomicAdd(&g_outcnt[s.z], 1u);
    atomicAdd(&g_outcnt[s.w], 1u);
    atomicAdd(&g_incnt[d.x], 1u);
    atomicAdd(&g_incnt[d.y], 1u);
    atomicAdd(&g_incnt[d.z], 1u);
    atomicAdd(&g_incnt[d.w], 1u);
}

// ---------------------------------------------------------------------------
// 2a. scan stage 1
// ---------------------------------------------------------------------------
__global__ __launch_bounds__(256) void scan1_kernel() {
    int tid  = threadIdx.x;
    int base = blockIdx.x * SCAN_TILE + tid * 4;
    unsigned int v[4], s = 0;
#pragma unroll
    for (int j = 0; j < 4; j++) {
        int idx = base + j;
        v[j] = (idx < N_NODES) ? g_incnt[idx] : 0u;
        s += v[j];
    }
    unsigned int x = s;
    int lane = tid & 31, warp = tid >> 5;
#pragma unroll
    for (int o = 1; o < 32; o <<= 1) {
        unsigned int y = __shfl_up_sync(0xffffffffu, x, o);
        if (lane >= o) x += y;
    }
    __shared__ unsigned int wsum[8];
    if (lane == 31) wsum[warp] = x;
    __syncthreads();
    if (warp == 0) {
        unsigned int w = (lane < 8) ? wsum[lane] : 0u;
#pragma unroll
        for (int o = 1; o < 8; o <<= 1) {
            unsigned int y = __shfl_up_sync(0xffffffffu, w, o);
            if (lane >= o) w += y;
        }
        if (lane < 8) wsum[lane] = w;
    }
    __syncthreads();
    unsigned int excl = x - s + (warp ? wsum[warp - 1] : 0u);
#pragma unroll
    for (int j = 0; j < 4; j++) {
        int idx = base + j;
        if (idx < N_NODES) g_off[idx] = excl;
        excl += v[j];
    }
    if (tid == 255) g_blk[blockIdx.x] = excl;
}

// ---------------------------------------------------------------------------
// 2b. scan stage 2
// ---------------------------------------------------------------------------
__global__ __launch_bounds__(512) void scan2_kernel() {
    __shared__ unsigned int bufA[512], bufB[512];
    int tid = threadIdx.x;
    unsigned int v = (tid < NB_SCAN) ? g_blk[tid] : 0u;
    bufA[tid] = v;
    __syncthreads();
    unsigned int *in = bufA, *out = bufB;
    for (int d = 1; d < 512; d <<= 1) {
        unsigned int x = in[tid];
        if (tid >= d) x += in[tid - d];
        out[tid] = x;
        __syncthreads();
        unsigned int* t = in; in = out; out = t;
    }
    if (tid < NB_SCAN) g_blk[tid] = in[tid] - v;
}

// ---------------------------------------------------------------------------
// 2c. scan stage 3 + node init
// ---------------------------------------------------------------------------
__global__ __launch_bounds__(256) void scan3_init_kernel(const float* __restrict__ y_in,
                                                         float* __restrict__ y) {
    int tid  = threadIdx.x;
    unsigned int add = g_blk[blockIdx.x];
    int base = blockIdx.x * SCAN_TILE + tid * 4;
#pragma unroll
    for (int j = 0; j < 4; j++) {
        int i = base + j;
        if (i >= N_NODES) break;
        unsigned int off = g_off[i] + add;
        g_off[i]    = off;
        g_cursor[i] = off;
        float ds = rsqrtf(fmaxf((float)g_outcnt[i], 1.0f));
        float dd = rsqrtf(fmaxf((float)g_incnt[i], 1.0f));
        g_ds[i] = ds;
        g_dd[i] = dd;
        float yv = y_in[i];
        yv = (yv == 0.0f) ? -1.0f : yv;
        y[i]    = yv;
        g_xs[i] = yv * ds;
    }
    if (blockIdx.x == 0 && tid == 0) g_off[N_NODES] = E_EDGES;
}

// ---------------------------------------------------------------------------
// 3. counting-sort scatter
// ---------------------------------------------------------------------------
__global__ void scatter_kernel(const int4* __restrict__ src4, const int4* __restrict__ dst4) {
    int i = blockIdx.x * blockDim.x + threadIdx.x;
    if (i >= NVEC) return;
    int4 s = __ldg(src4 + i);
    int4 d = __ldg(dst4 + i);
    unsigned int p0 = atomicAdd(&g_cursor[d.x], 1u);
    unsigned int p1 = atomicAdd(&g_cursor[d.y], 1u);
    unsigned int p2 = atomicAdd(&g_cursor[d.z], 1u);
    unsigned int p3 = atomicAdd(&g_cursor[d.w], 1u);
    g_srcSorted[p0] = (unsigned int)s.x;
    g_srcSorted[p1] = (unsigned int)s.y;
    g_srcSorted[p2] = (unsigned int)s.z;
    g_srcSorted[p3] = (unsigned int)s.w;
}

// ---------------------------------------------------------------------------
// Warp-cooperative aggregate for 32 consecutive nodes. Returns this lane's
// node aggregate (node = warpNode0 + lane). Index loads coalesced; one
// random-gather wavefront per edge (the floor).
// ---------------------------------------------------------------------------
__device__ __forceinline__ float warp_seg_gather(const float* __restrict__ vals,
                                                 unsigned int my_lo, unsigned int my_hi,
                                                 int lane) {
    float myAgg = 0.0f;
#pragma unroll 1
    for (int k = 0; k < 32; k++) {
        unsigned int lo = __shfl_sync(0xffffffffu, my_lo, k);
        unsigned int hi = __shfl_sync(0xffffffffu, my_hi, k);
        float a = 0.0f;
        for (unsigned int i = lo + lane; i < hi; i += 32) {
            a += __ldg(vals + __ldg(g_srcSorted + i));
        }
#pragma unroll
        for (int o = 16; o > 0; o >>= 1)
            a += __shfl_xor_sync(0xffffffffu, a, o);
        if (lane == k) myAgg = a;
    }
    return myAgg;
}

// ---------------------------------------------------------------------------
// 4a. fused pass A: agg = A·xs ; fc+resid+LN+PReLU + layer-2 fc -> g_x2
//     one warp per 32 nodes
// ---------------------------------------------------------------------------
__global__ __launch_bounds__(256) void passA_kernel(const float* __restrict__ y,
        const float* __restrict__ W1,  const float* __restrict__ b1,
        const float* __restrict__ Wres,
        const float* __restrict__ lng, const float* __restrict__ lnb,
        const float* __restrict__ pa,
        const float* __restrict__ W2,  const float* __restrict__ b2) {
    int gt = blockIdx.x * blockDim.x + threadIdx.x;
    int w  = gt >> 5;
    if (w >= NWARPS) return;
    int lane = gt & 31;
    int n = w * 32 + lane;

    unsigned int my_lo = g_off[n];
    unsigned int my_hi = g_off[n + 1];
    float a = warp_seg_gather(g_xs, my_lo, my_hi, lane);

    float yv = __ldg(y + n);
    float ds = g_ds[n];
    float dd = g_dd[n];
    float alpha = __ldg(pa);
    float bias2 = __ldg(b2);

    float r[8]; float mu = 0.f;
#pragma unroll
    for (int j = 0; j < 8; j++) {
        r[j] = (a * __ldg(W1 + j) + __ldg(b1 + j)) * dd + yv * __ldg(Wres + j);
        mu += r[j];
    }
    mu *= 0.125f;
    float var = 0.f;
#pragma unroll
    for (int j = 0; j < 8; j++) { float u = r[j] - mu; var += u * u; }
    var *= 0.125f;
    float inv = rsqrtf(var + 1e-5f);
    float dot = 0.f;
#pragma unroll
    for (int j = 0; j < 8; j++) {
        float u = (r[j] - mu) * inv * __ldg(lng + j) + __ldg(lnb + j);
        u = (u >= 0.f) ? u : alpha * u;
        dot += u * __ldg(W2 + j);
    }
    g_x2[n] = ds * dot + bias2;
}

// ---------------------------------------------------------------------------
// 4b. fused pass B: agg2 = A·x2 ; y += dd*agg2 ; xs = y*ds
// ---------------------------------------------------------------------------
__global__ __launch_bounds__(256) void passB_kernel(float* __restrict__ y) {
    int gt = blockIdx.x * blockDim.x + threadIdx.x;
    int w  = gt >> 5;
    if (w >= NWARPS) return;
    int lane = gt & 31;
    int n = w * 32 + lane;

    unsigned int my_lo = g_off[n];
    unsigned int my_hi = g_off[n + 1];
    float a = warp_seg_gather(g_x2, my_lo, my_hi, lane);

    float yv = y[n] + a * g_dd[n];
    y[n]    = yv;
    g_xs[n] = yv * g_ds[n];
}

// ---------------------------------------------------------------------------
// launch
// ---------------------------------------------------------------------------
extern "C" void kernel_launch(void* const* d_in, const int* in_sizes, int n_in,
                              void* d_out, int out_size) {
    const float* y_in = (const float*)d_in[0];
    const int*   src  = (const int*)d_in[1];
    const int*   dst  = (const int*)d_in[2];
    const float* W1   = (const float*)d_in[3];
    const float* b1   = (const float*)d_in[4];
    const float* Wres = (const float*)d_in[5];
    const float* lng  = (const float*)d_in[6];
    const float* lnb  = (const float*)d_in[7];
    const float* pa   = (const float*)d_in[8];
    const float* W2   = (const float*)d_in[9];
    const float* b2   = (const float*)d_in[10];
    float* y = (float*)d_out;

    const int TB = 256;
    int nb_n = (N_NODES + TB - 1) / TB;
    int nb_e = (NVEC + TB - 1) / TB;
    int nb_w = (NWARPS * 32 + TB - 1) / TB;   // warp-per-32-nodes grids

    zero_kernel<<<nb_n, TB>>>();
    count_kernel<<<nb_e, TB>>>((const int4*)src, (const int4*)dst);
    scan1_kernel<<<NB_SCAN, 256>>>();
    scan2_kernel<<<1, 512>>>();
    scan3_init_kernel<<<NB_SCAN, 256>>>(y_in, y);
    scatter_kernel<<<nb_e, TB>>>((const int4*)src, (const int4*)dst);

    for (int l = 0; l < 4; l++) {
        passA_kernel<<<nb_w, TB>>>(y, W1, b1, Wres, lng, lnb, pa, W2, b2);
        passB_kernel<<<nb_w, TB>>>(y);
    }
}

// round 5
// speedup vs baseline: 1.3287x; 1.0798x over previous
#include <cuda_runtime.h>

#define N_NODES   500000
#define E_EDGES   16000000
#define NVEC      (E_EDGES / 4)
#define NWARPS    (N_NODES / 32)         // 15625 warps, 32 nodes each
#define PAD       96                     // slots per node bucket (P(overflow) ~ 1e-20)

// ---------------------------------------------------------------------------
// Static scratch (allocation-free rule)
// ---------------------------------------------------------------------------
__device__ unsigned int  g_outcnt[N_NODES];
__device__ float         g_ds[N_NODES];              // out_deg^-0.5
__device__ float         g_dd[N_NODES];              // in_deg^-0.5
__device__ float         g_xs[N_NODES];              // y * ds
__device__ float         g_x2[N_NODES];              // layer-2 message
__device__ unsigned int  g_end[N_NODES];             // bucket end (=cursor after scatter)
__device__ unsigned int  g_cursor[N_NODES];
__device__ unsigned int  g_srcSorted[N_NODES * PAD]; // padded buckets of src ids by dst

// ---------------------------------------------------------------------------
// 0. init cursors + zero out-degree
// ---------------------------------------------------------------------------
__global__ void init_cursor_kernel() {
    int i = blockIdx.x * blockDim.x + threadIdx.x;
    if (i < N_NODES) {
        g_cursor[i] = (unsigned int)i * PAD;
        g_outcnt[i] = 0u;
    }
}

// ---------------------------------------------------------------------------
// 1. fused scatter: place src ids into dst buckets + out-degree REDs
// ---------------------------------------------------------------------------
__global__ void scatter_kernel(const int4* __restrict__ src4, const int4* __restrict__ dst4) {
    int i = blockIdx.x * blockDim.x + threadIdx.x;
    if (i >= NVEC) return;
    int4 s = __ldg(src4 + i);
    int4 d = __ldg(dst4 + i);
    atomicAdd(&g_outcnt[s.x], 1u);
    atomicAdd(&g_outcnt[s.y], 1u);
    atomicAdd(&g_outcnt[s.z], 1u);
    atomicAdd(&g_outcnt[s.w], 1u);
    unsigned int p0 = atomicAdd(&g_cursor[d.x], 1u);
    unsigned int p1 = atomicAdd(&g_cursor[d.y], 1u);
    unsigned int p2 = atomicAdd(&g_cursor[d.z], 1u);
    unsigned int p3 = atomicAdd(&g_cursor[d.w], 1u);
    g_srcSorted[p0] = (unsigned int)s.x;
    g_srcSorted[p1] = (unsigned int)s.y;
    g_srcSorted[p2] = (unsigned int)s.z;
    g_srcSorted[p3] = (unsigned int)s.w;
}

// ---------------------------------------------------------------------------
// 2. node init: degree norms (in-degree from cursor), y sign fix, first msg
// ---------------------------------------------------------------------------
__global__ void init_kernel(const float* __restrict__ y_in, float* __restrict__ y) {
    int i = blockIdx.x * blockDim.x + threadIdx.x;
    if (i >= N_NODES) return;
    unsigned int end = g_cursor[i];
    g_end[i] = end;
    float indeg = (float)(end - (unsigned int)i * PAD);
    float ds = rsqrtf(fmaxf((float)g_outcnt[i], 1.0f));
    float dd = rsqrtf(fmaxf(indeg, 1.0f));
    g_ds[i] = ds;
    g_dd[i] = dd;
    float yv = y_in[i];
    yv = (yv == 0.0f) ? -1.0f : yv;
    y[i]    = yv;
    g_xs[i] = yv * ds;
}

// ---------------------------------------------------------------------------
// Warp-cooperative aggregate for 32 consecutive nodes. Returns this lane's
// node aggregate (node = warpNode0 + lane).
// ---------------------------------------------------------------------------
__device__ __forceinline__ float warp_seg_gather(const float* __restrict__ vals,
                                                 unsigned int my_lo, unsigned int my_hi,
                                                 int lane) {
    float myAgg = 0.0f;
#pragma unroll 1
    for (int k = 0; k < 32; k++) {
        unsigned int lo = __shfl_sync(0xffffffffu, my_lo, k);
        unsigned int hi = __shfl_sync(0xffffffffu, my_hi, k);
        float a = 0.0f;
        for (unsigned int i = lo + lane; i < hi; i += 32) {
            a += __ldg(vals + __ldg(g_srcSorted + i));
        }
#pragma unroll
        for (int o = 16; o > 0; o >>= 1)
            a += __shfl_xor_sync(0xffffffffu, a, o);
        if (lane == k) myAgg = a;
    }
    return myAgg;
}

// ---------------------------------------------------------------------------
// 3a. fused pass A: agg = A·xs ; fc+resid+LN+PReLU + layer-2 fc -> g_x2
//     one warp per 32 nodes
// ---------------------------------------------------------------------------
__global__ __launch_bounds__(256) void passA_kernel(const float* __restrict__ y,
        const float* __restrict__ W1,  const float* __restrict__ b1,
        const float* __restrict__ Wres,
        const float* __restrict__ lng, const float* __restrict__ lnb,
        const float* __restrict__ pa,
        const float* __restrict__ W2,  const float* __restrict__ b2) {
    int gt = blockIdx.x * blockDim.x + threadIdx.x;
    int w  = gt >> 5;
    if (w >= NWARPS) return;
    int lane = gt & 31;
    int n = w * 32 + lane;

    unsigned int my_lo = (unsigned int)n * PAD;
    unsigned int my_hi = __ldg(g_end + n);
    float a = warp_seg_gather(g_xs, my_lo, my_hi, lane);

    float yv = __ldg(y + n);
    float ds = g_ds[n];
    float dd = g_dd[n];
    float alpha = __ldg(pa);
    float bias2 = __ldg(b2);

    float r[8]; float mu = 0.f;
#pragma unroll
    for (int j = 0; j < 8; j++) {
        r[j] = (a * __ldg(W1 + j) + __ldg(b1 + j)) * dd + yv * __ldg(Wres + j);
        mu += r[j];
    }
    mu *= 0.125f;
    float var = 0.f;
#pragma unroll
    for (int j = 0; j < 8; j++) { float u = r[j] - mu; var += u * u; }
    var *= 0.125f;
    float inv = rsqrtf(var + 1e-5f);
    float dot = 0.f;
#pragma unroll
    for (int j = 0; j < 8; j++) {
        float u = (r[j] - mu) * inv * __ldg(lng + j) + __ldg(lnb + j);
        u = (u >= 0.f) ? u : alpha * u;
        dot += u * __ldg(W2 + j);
    }
    g_x2[n] = ds * dot + bias2;
}

// ---------------------------------------------------------------------------
// 3b. fused pass B: agg2 = A·x2 ; y += dd*agg2 ; xs = y*ds
// ---------------------------------------------------------------------------
__global__ __launch_bounds__(256) void passB_kernel(float* __restrict__ y) {
    int gt = blockIdx.x * blockDim.x + threadIdx.x;
    int w  = gt >> 5;
    if (w >= NWARPS) return;
    int lane = gt & 31;
    int n = w * 32 + lane;

    unsigned int my_lo = (unsigned int)n * PAD;
    unsigned int my_hi = __ldg(g_end + n);
    float a = warp_seg_gather(g_x2, my_lo, my_hi, lane);

    float yv = y[n] + a * g_dd[n];
    y[n]    = yv;
    g_xs[n] = yv * g_ds[n];
}

// ---------------------------------------------------------------------------
// launch
// ---------------------------------------------------------------------------
extern "C" void kernel_launch(void* const* d_in, const int* in_sizes, int n_in,
                              void* d_out, int out_size) {
    const float* y_in = (const float*)d_in[0];
    const int*   src  = (const int*)d_in[1];
    const int*   dst  = (const int*)d_in[2];
    const float* W1   = (const float*)d_in[3];
    const float* b1   = (const float*)d_in[4];
    const float* Wres = (const float*)d_in[5];
    const float* lng  = (const float*)d_in[6];
    const float* lnb  = (const float*)d_in[7];
    const float* pa   = (const float*)d_in[8];
    const float* W2   = (const float*)d_in[9];
    const float* b2   = (const float*)d_in[10];
    float* y = (float*)d_out;

    const int TB = 256;
    int nb_n = (N_NODES + TB - 1) / TB;
    int nb_e = (NVEC + TB - 1) / TB;
    int nb_w = (NWARPS * 32 + TB - 1) / TB;

    init_cursor_kernel<<<nb_n, TB>>>();
    scatter_kernel<<<nb_e, TB>>>((const int4*)src, (const int4*)dst);
    init_kernel<<<nb_n, TB>>>(y_in, y);

    for (int l = 0; l < 4; l++) {
        passA_kernel<<<nb_w, TB>>>(y, W1, b1, Wres, lng, lnb, pa, W2, b2);
        passB_kernel<<<nb_w, TB>>>(y);
    }
}